// round 9
// baseline (speedup 1.0000x reference)
#include <cuda_runtime.h>
#include <stdint.h>

#define NN 50000
#define EE 320000
#define FF 256
#define KK 2
#define KDIM 512
#define KITERS 16        // KDIM / 32

// Scratch (allocation-free rule: __device__ globals)
// A-side operands stored with k permuted within each 8-group: stored {0,4,1,5,2,6,3,7}
__device__ unsigned g_xptf[(size_t)NN * FF];     // tf32(A_hat @ x), k-permuted
__device__ unsigned g_xtf[(size_t)NN * FF];      // tf32(x), k-permuted
__device__ unsigned g_wtfT[2][KK][FF][FF];       // tf32 W transposed: [phase][km][n][k_stored]
__device__ int   g_degi[NN];
__device__ float g_dinv[NN];
__device__ int   g_rowstart[NN + 1];
__device__ int   g_cursor[NN];
__device__ int   g_csr_src[EE];
__device__ float g_csr_w[EE];
__device__ int   g_is64;

__device__ __forceinline__ unsigned f2tf32(float f) {
    unsigned r;
    asm("cvt.rna.tf32.f32 %0, %1;" : "=r"(r) : "f"(f));
    return r;
}

__device__ __forceinline__ int load_idx(const void* ei, int which, int e) {
    if (g_is64) return (int)((const long long*)ei)[(size_t)which * EE + e];
    return ((const int*)ei)[(size_t)which * EE + e];
}

// ---------------------------------------------------------------------------
// 1) zero degrees + dtype sniff (block 0)
// ---------------------------------------------------------------------------
__global__ void zero_sniff_kernel(const int* __restrict__ ei32) {
    int i = blockIdx.x * blockDim.x + threadIdx.x;
    if (i < NN) g_degi[i] = 0;
    if (blockIdx.x == 0 && threadIdx.x == 0) {
        int any = 0;
        for (int j = 0; j < 256; ++j) any |= ei32[2 * j + 1];
        g_is64 = (any == 0) ? 1 : 0;
    }
}

// ---------------------------------------------------------------------------
// 2) degree count
// ---------------------------------------------------------------------------
__global__ void deg_kernel(const void* __restrict__ ei) {
    int e = blockIdx.x * blockDim.x + threadIdx.x;
    if (e < EE) atomicAdd(&g_degi[load_idx(ei, 1, e)], 1);
}

// ---------------------------------------------------------------------------
// 3) scan (+ dinv folded in)
// ---------------------------------------------------------------------------
#define SCAN_CH 49

__global__ __launch_bounds__(1024) void scan_kernel() {
    __shared__ int s[1024];
    const int t = threadIdx.x;
    const int base = t * SCAN_CH;
    int sum = 0;
#pragma unroll
    for (int i = 0; i < SCAN_CH; ++i) {
        int idx = base + i;
        if (idx < NN) {
            int d = g_degi[idx];
            sum += d;
            g_dinv[idx] = (d > 0) ? rsqrtf((float)d) : 0.0f;
        }
    }
    s[t] = sum;
    __syncthreads();
    for (int off = 1; off < 1024; off <<= 1) {
        int v = (t >= off) ? s[t - off] : 0;
        __syncthreads();
        s[t] += v;
        __syncthreads();
    }
    int run = (t == 0) ? 0 : s[t - 1];
#pragma unroll
    for (int i = 0; i < SCAN_CH; ++i) {
        int idx = base + i;
        if (idx < NN) {
            g_rowstart[idx] = run;
            run += g_degi[idx];
            g_cursor[idx] = 0;
        }
    }
    if (t == 1023) g_rowstart[NN] = run;
}

// ---------------------------------------------------------------------------
// 4) CSR fill
// ---------------------------------------------------------------------------
__global__ void fill_csr_kernel(const void* __restrict__ ei) {
    int e = blockIdx.x * blockDim.x + threadIdx.x;
    if (e >= EE) return;
    int src = load_idx(ei, 0, e);
    int dst = load_idx(ei, 1, e);
    int pos = atomicAdd(&g_cursor[dst], 1);
    int idx = g_rowstart[dst] + pos;
    g_csr_src[idx] = src;
    g_csr_w[idx] = g_dinv[src] * g_dinv[dst];
}

// ---------------------------------------------------------------------------
// 5) prep: gather(xp) + cvt_x + cvt_w fused via disjoint block ranges.
//    gather: 64 thr/node; thread owns stored uint4 chunk c (0..63):
//      g=c>>1, h=c&1, L0=8g+2h -> logical {L0, L0+4, L0+1, L0+5}
//    4-edge unroll for MLP.
// ---------------------------------------------------------------------------
#define GATHER_BLOCKS (NN * 64 / 256)            // 12500
#define CVTX_GROUPS (NN * FF / 8)                // 1,600,000
#define CVTX_BLOCKS ((CVTX_GROUPS + 255) / 256)  // 6250
#define CVTW_THREADS (2 * KK * FF * (FF / 8))    // 65536
#define CVTW_BLOCKS (CVTW_THREADS / 256)         // 256

__global__ __launch_bounds__(256) void prep_kernel(
    const float* __restrict__ x, const float* __restrict__ wi,
    const float* __restrict__ wr)
{
    const int bid = blockIdx.x;
    if (bid < GATHER_BLOCKS) {
        // ---- gather: xp = A_hat @ x, written permuted+tf32 ----
        const int gidx = bid * 256 + threadIdx.x;
        const int n = gidx >> 6;
        const int c = gidx & 63;
        const int g = c >> 1, h = c & 1;
        const int L0 = 8 * g + 2 * h;            // logical features: L0, L0+1, L0+4, L0+5

        float a0 = 0.f, a1 = 0.f, a2 = 0.f, a3 = 0.f;  // logical L0, L0+4, L0+1, L0+5
        const int beg = g_rowstart[n];
        const int end = g_rowstart[n + 1];
        int e = beg;
        for (; e + 3 < end; e += 4) {
            int s0 = g_csr_src[e], s1 = g_csr_src[e+1], s2 = g_csr_src[e+2], s3 = g_csr_src[e+3];
            float w0 = g_csr_w[e], w1 = g_csr_w[e+1], w2 = g_csr_w[e+2], w3 = g_csr_w[e+3];
            float2 p0 = *(const float2*)(x + (size_t)s0 * FF + L0);
            float2 q0 = *(const float2*)(x + (size_t)s0 * FF + L0 + 4);
            float2 p1 = *(const float2*)(x + (size_t)s1 * FF + L0);
            float2 q1 = *(const float2*)(x + (size_t)s1 * FF + L0 + 4);
            float2 p2 = *(const float2*)(x + (size_t)s2 * FF + L0);
            float2 q2 = *(const float2*)(x + (size_t)s2 * FF + L0 + 4);
            float2 p3 = *(const float2*)(x + (size_t)s3 * FF + L0);
            float2 q3 = *(const float2*)(x + (size_t)s3 * FF + L0 + 4);
            a0 += w0 * p0.x + w1 * p1.x + w2 * p2.x + w3 * p3.x;
            a2 += w0 * p0.y + w1 * p1.y + w2 * p2.y + w3 * p3.y;
            a1 += w0 * q0.x + w1 * q1.x + w2 * q2.x + w3 * q3.x;
            a3 += w0 * q0.y + w1 * q1.y + w2 * q2.y + w3 * q3.y;
        }
        for (; e < end; ++e) {
            int s0 = g_csr_src[e];
            float w0 = g_csr_w[e];
            float2 p0 = *(const float2*)(x + (size_t)s0 * FF + L0);
            float2 q0 = *(const float2*)(x + (size_t)s0 * FF + L0 + 4);
            a0 += w0 * p0.x; a2 += w0 * p0.y;
            a1 += w0 * q0.x; a3 += w0 * q0.y;
        }
        // stored order within chunk: {L0, L0+4, L0+1, L0+5}
        *(uint4*)(g_xptf + (size_t)n * FF + c * 4) =
            make_uint4(f2tf32(a0), f2tf32(a1), f2tf32(a2), f2tf32(a3));
    } else if (bid < GATHER_BLOCKS + CVTX_BLOCKS) {
        // ---- cvt_x: permute+convert x -> g_xtf ----
        const int gi = (bid - GATHER_BLOCKS) * 256 + threadIdx.x;
        if (gi < CVTX_GROUPS) {
            const float* p = x + (size_t)gi * 8;
            float4 v0 = *(const float4*)(p);
            float4 v1 = *(const float4*)(p + 4);
            unsigned* o = g_xtf + (size_t)gi * 8;
            // stored {0,4,1,5, 2,6,3,7}
            *(uint4*)(o)     = make_uint4(f2tf32(v0.x), f2tf32(v1.x), f2tf32(v0.y), f2tf32(v1.y));
            *(uint4*)(o + 4) = make_uint4(f2tf32(v0.z), f2tf32(v1.z), f2tf32(v0.w), f2tf32(v1.w));
        }
    } else {
        // ---- cvt_w: transpose + permute + convert weights ----
        // thread -> (mat 0..3, grp 0..31, n 0..255), n fastest for coalesced reads
        const int ti = (bid - GATHER_BLOCKS - CVTX_BLOCKS) * 256 + threadIdx.x;
        if (ti < CVTW_THREADS) {
            const int n = ti & 255;
            const int grp = (ti >> 8) & 31;
            const int mat = ti >> 13;            // 0..3 = phase*2+km
            const float* src = (mat < 2) ? wi : wr;
            const int km = mat & 1;
            src += (size_t)km * FF * FF;
            float v[8];
#pragma unroll
            for (int j = 0; j < 8; ++j)
                v[j] = src[(size_t)(grp * 8 + j) * FF + n];
            unsigned* o = &g_wtfT[mat >> 1][km][n][grp * 8];
            *(uint4*)(o)     = make_uint4(f2tf32(v[0]), f2tf32(v[4]), f2tf32(v[1]), f2tf32(v[5]));
            *(uint4*)(o + 4) = make_uint4(f2tf32(v[2]), f2tf32(v[6]), f2tf32(v[3]), f2tf32(v[7]));
        }
    }
}

// ---------------------------------------------------------------------------
// 6) Fused tf32 GEMM + epilogue; cp.async 3-stage; fragment-packed LDS.64.
// Block 128(M) x 128(N), BK=32, 512 threads (4Mx4N warps, 32x32 warp tile).
// As[128][40], Bs[2][128][40] (k_stored inner), all uint.
// ---------------------------------------------------------------------------
#define AS_STRIDE 40
#define BS_STRIDE 40
#define AS_WORDS (128 * AS_STRIDE)                     // 5120
#define BS_WORDS (2 * 128 * BS_STRIDE)                 // 10240
#define STAGE_WORDS (AS_WORDS + BS_WORDS)              // 15360
#define NSTAGES 3
#define GEMM_SMEM (NSTAGES * STAGE_WORDS * 4)          // 184320 B

__device__ __forceinline__ void cp16(unsigned smaddr, const void* gptr, int valid) {
    asm volatile("cp.async.cg.shared.global [%0], [%1], 16, %2;"
                 :: "r"(smaddr), "l"(gptr), "r"(valid ? 16 : 0));
}
__device__ __forceinline__ void cp_commit() {
    asm volatile("cp.async.commit_group;");
}
template <int N>
__device__ __forceinline__ void cp_wait() {
    asm volatile("cp.async.wait_group %0;" :: "n"(N));
}

__device__ __forceinline__ void mma_tf32(float* c, const unsigned* a, const unsigned* b) {
    asm volatile(
        "mma.sync.aligned.m16n8k8.row.col.f32.tf32.tf32.f32 "
        "{%0,%1,%2,%3}, {%4,%5,%6,%7}, {%8,%9}, {%0,%1,%2,%3};\n"
        : "+f"(c[0]), "+f"(c[1]), "+f"(c[2]), "+f"(c[3])
        : "r"(a[0]), "r"(a[1]), "r"(a[2]), "r"(a[3]), "r"(b[0]), "r"(b[1]));
}

__global__ __launch_bounds__(512, 1) void fused_gemm_kernel(
    const float* __restrict__ x, const float* __restrict__ bias,
    float* __restrict__ out)
{
    extern __shared__ unsigned sm[];

    const int tid = threadIdx.x;
    const int lane = tid & 31;
    const int wid = tid >> 5;
    const int warpM = wid & 3;
    const int warpN = wid >> 2;
    const int tileRow = blockIdx.y * 128;
    const int colBase = blockIdx.x * 128;

    auto issue = [&](int it, int st) {
        const int phase = it >> 3;
        const int kkL = (it & 7) * 32;
        const unsigned* Atf = phase ? g_xtf : g_xptf;
        unsigned* As = sm + st * STAGE_WORDS;
        unsigned* Bs = As + AS_WORDS;
        unsigned as_base = (unsigned)__cvta_generic_to_shared(As);
        unsigned bs_base = (unsigned)__cvta_generic_to_shared(Bs);
        // A: 128 rows x 32 k = 1024 uint4 -> 2 per thread
#pragma unroll
        for (int i = 0; i < 2; ++i) {
            int ii = i * 512 + tid;
            int m = ii >> 3, kq = ii & 7;
            int row = tileRow + m;
            int valid = row < NN;
            int rowc = valid ? row : 0;
            cp16(as_base + (m * AS_STRIDE + kq * 4) * 4,
                 Atf + (size_t)rowc * FF + kkL + kq * 4, valid);
        }
        // B: 2 km x 128 n x 32 k = 2048 uint4 -> 4 per thread
#pragma unroll
        for (int i = 0; i < 4; ++i) {
            int ii = i * 512 + tid;
            int km = ii >> 10, n = (ii >> 3) & 127, kq = ii & 7;
            cp16(bs_base + (km * 128 * BS_STRIDE + n * BS_STRIDE + kq * 4) * 4,
                 &g_wtfT[phase][km][colBase + n][kkL + kq * 4], 1);
        }
        cp_commit();
    };

    float acc[2][2][4][4] = {};

    issue(0, 0);
    issue(1, 1);
    issue(2, 2);

    for (int it = 0; it < KITERS; ++it) {
        if (it < KITERS - 2)       cp_wait<2>();
        else if (it == KITERS - 2) cp_wait<1>();
        else                       cp_wait<0>();
        __syncthreads();

        const int st = it % NSTAGES;
        const unsigned* As = sm + st * STAGE_WORDS;
        const unsigned* Bs = As + AS_WORDS;
        const int q2 = 2 * (lane & 3);

#pragma unroll
        for (int ks = 0; ks < 4; ++ks) {
            const int k8 = ks * 8;
            unsigned a[2][4];
#pragma unroll
            for (int mt = 0; mt < 2; ++mt) {
                int mrow = warpM * 32 + mt * 16 + (lane >> 2);
                uint2 lo = *(const uint2*)(As + mrow * AS_STRIDE + k8 + q2);        // (a0, a2)
                uint2 hi = *(const uint2*)(As + (mrow + 8) * AS_STRIDE + k8 + q2);  // (a1, a3)
                a[mt][0] = lo.x; a[mt][1] = hi.x; a[mt][2] = lo.y; a[mt][3] = hi.y;
            }
            unsigned b[2][4][2];
#pragma unroll
            for (int km = 0; km < 2; ++km)
#pragma unroll
                for (int nt = 0; nt < 4; ++nt) {
                    int ncol = warpN * 32 + nt * 8 + (lane >> 2);
                    uint2 bb = *(const uint2*)(Bs + km * 128 * BS_STRIDE
                                               + ncol * BS_STRIDE + k8 + q2);       // (b0, b1)
                    b[km][nt][0] = bb.x; b[km][nt][1] = bb.y;
                }
#pragma unroll
            for (int km = 0; km < 2; ++km)
#pragma unroll
                for (int mt = 0; mt < 2; ++mt)
#pragma unroll
                    for (int nt = 0; nt < 4; ++nt)
                        mma_tf32(acc[km][mt][nt], a[mt], b[km][nt]);
        }
        __syncthreads();
        if (it + NSTAGES < KITERS) issue(it + NSTAGES, st);
    }

    // Epilogue: out = x + relu(0.5*(relu(C0+b0)+relu(C1+b1)))
#pragma unroll
    for (int mt = 0; mt < 2; ++mt) {
#pragma unroll
        for (int nt = 0; nt < 4; ++nt) {
            const int col = colBase + warpN * 32 + nt * 8 + 2 * (lane & 3);
            const float bi00 = bias[col],      bi01 = bias[col + 1];
            const float bi10 = bias[FF + col], bi11 = bias[FF + col + 1];
            const int r0 = tileRow + warpM * 32 + mt * 16 + (lane >> 2);

            if (r0 < NN) {
                float2 xv = *(const float2*)(x + (size_t)r0 * FF + col);
                float u0 = fmaxf(acc[0][mt][nt][0] + bi00, 0.f);
                float v0 = fmaxf(acc[1][mt][nt][0] + bi10, 0.f);
                float u1 = fmaxf(acc[0][mt][nt][1] + bi01, 0.f);
                float v1 = fmaxf(acc[1][mt][nt][1] + bi11, 0.f);
                float2 o;
                o.x = xv.x + fmaxf(0.5f * (u0 + v0), 0.f);
                o.y = xv.y + fmaxf(0.5f * (u1 + v1), 0.f);
                *(float2*)(out + (size_t)r0 * FF + col) = o;
            }
            const int r1 = r0 + 8;
            if (r1 < NN) {
                float2 xv = *(const float2*)(x + (size_t)r1 * FF + col);
                float u0 = fmaxf(acc[0][mt][nt][2] + bi00, 0.f);
                float v0 = fmaxf(acc[1][mt][nt][2] + bi10, 0.f);
                float u1 = fmaxf(acc[0][mt][nt][3] + bi01, 0.f);
                float v1 = fmaxf(acc[1][mt][nt][3] + bi11, 0.f);
                float2 o;
                o.x = xv.x + fmaxf(0.5f * (u0 + v0), 0.f);
                o.y = xv.y + fmaxf(0.5f * (u1 + v1), 0.f);
                *(float2*)(out + (size_t)r1 * FF + col) = o;
            }
        }
    }
}

// ---------------------------------------------------------------------------
// launch: 6 kernels, GEMM is #6 (ncu -s 5 -c 1 captures it)
// ---------------------------------------------------------------------------
extern "C" void kernel_launch(void* const* d_in, const int* in_sizes, int n_in,
                              void* d_out, int out_size) {
    const float* x    = (const float*)d_in[0];
    const void* ei    = d_in[1];
    const float* wi   = (const float*)d_in[2];
    const float* wr   = (const float*)d_in[3];
    const float* bias = (const float*)d_in[4];
    float* out        = (float*)d_out;

    static int smem_set = 0;
    if (!smem_set) {
        cudaFuncSetAttribute(fused_gemm_kernel,
                             cudaFuncAttributeMaxDynamicSharedMemorySize, GEMM_SMEM);
        smem_set = 1;
    }

    zero_sniff_kernel<<<(NN + 255) / 256, 256>>>((const int*)ei);      // 1
    deg_kernel<<<(EE + 255) / 256, 256>>>(ei);                         // 2
    scan_kernel<<<1, 1024>>>();                                        // 3
    fill_csr_kernel<<<(EE + 255) / 256, 256>>>(ei);                    // 4
    prep_kernel<<<GATHER_BLOCKS + CVTX_BLOCKS + CVTW_BLOCKS, 256>>>(x, wi, wr);  // 5
    dim3 ggrid(FF / 128, (NN + 127) / 128);                            // (2, 391)
    fused_gemm_kernel<<<ggrid, 512, GEMM_SMEM>>>(x, bias, out);        // 6
}

// round 10
// speedup vs baseline: 1.2903x; 1.2903x over previous
#include <cuda_runtime.h>
#include <cuda_fp16.h>
#include <stdint.h>

#define NN 50000
#define EE 320000
#define FF 256
#define KK 2
#define KDIM 512
#define KITERS 16        // KDIM / 32 (BK = 32 halves)

// Scratch (allocation-free rule: __device__ globals). All fp16 stored as packed half2 words.
__device__ unsigned g_xph[(size_t)NN * FF / 2];      // half2(A_hat @ x)
__device__ unsigned g_xh[(size_t)NN * FF / 2];       // half2(x)
__device__ unsigned g_wh[2][KK][FF][FF / 2];         // half2 W^T: [phase][km][n][k/2]
__device__ int   g_degi[NN];
__device__ float g_dinv[NN];
__device__ int   g_rowstart[NN + 1];
__device__ int   g_cursor[NN];
__device__ int   g_csr_src[EE];
__device__ float g_csr_w[EE];
__device__ int   g_is64;

__device__ __forceinline__ unsigned pack_h2(float a, float b) {
    __half2 h = __floats2half2_rn(a, b);
    return *(unsigned*)&h;
}

__device__ __forceinline__ int load_idx(const void* ei, int which, int e) {
    if (g_is64) return (int)((const long long*)ei)[(size_t)which * EE + e];
    return ((const int*)ei)[(size_t)which * EE + e];
}

// ---------------------------------------------------------------------------
// 1) zero degrees + dtype sniff
// ---------------------------------------------------------------------------
__global__ void zero_sniff_kernel(const int* __restrict__ ei32) {
    int i = blockIdx.x * blockDim.x + threadIdx.x;
    if (i < NN) g_degi[i] = 0;
    if (blockIdx.x == 0 && threadIdx.x == 0) {
        int any = 0;
        for (int j = 0; j < 256; ++j) any |= ei32[2 * j + 1];
        g_is64 = (any == 0) ? 1 : 0;
    }
}

// ---------------------------------------------------------------------------
// 2) degree count
// ---------------------------------------------------------------------------
__global__ void deg_kernel(const void* __restrict__ ei) {
    int e = blockIdx.x * blockDim.x + threadIdx.x;
    if (e < EE) atomicAdd(&g_degi[load_idx(ei, 1, e)], 1);
}

// ---------------------------------------------------------------------------
// 3) scan (+ dinv folded in)
// ---------------------------------------------------------------------------
#define SCAN_CH 49

__global__ __launch_bounds__(1024) void scan_kernel() {
    __shared__ int s[1024];
    const int t = threadIdx.x;
    const int base = t * SCAN_CH;
    int sum = 0;
#pragma unroll
    for (int i = 0; i < SCAN_CH; ++i) {
        int idx = base + i;
        if (idx < NN) {
            int d = g_degi[idx];
            sum += d;
            g_dinv[idx] = (d > 0) ? rsqrtf((float)d) : 0.0f;
        }
    }
    s[t] = sum;
    __syncthreads();
    for (int off = 1; off < 1024; off <<= 1) {
        int v = (t >= off) ? s[t - off] : 0;
        __syncthreads();
        s[t] += v;
        __syncthreads();
    }
    int run = (t == 0) ? 0 : s[t - 1];
#pragma unroll
    for (int i = 0; i < SCAN_CH; ++i) {
        int idx = base + i;
        if (idx < NN) {
            g_rowstart[idx] = run;
            run += g_degi[idx];
            g_cursor[idx] = 0;
        }
    }
    if (t == 1023) g_rowstart[NN] = run;
}

// ---------------------------------------------------------------------------
// 4) CSR fill
// ---------------------------------------------------------------------------
__global__ void fill_csr_kernel(const void* __restrict__ ei) {
    int e = blockIdx.x * blockDim.x + threadIdx.x;
    if (e >= EE) return;
    int src = load_idx(ei, 0, e);
    int dst = load_idx(ei, 1, e);
    int pos = atomicAdd(&g_cursor[dst], 1);
    int idx = g_rowstart[dst] + pos;
    g_csr_src[idx] = src;
    g_csr_w[idx] = g_dinv[src] * g_dinv[dst];
}

// ---------------------------------------------------------------------------
// 5) prep: gather(xp)->fp16 + cvt_x->fp16 + cvt_w(transpose)->fp16, one kernel.
//    gather: warp per node, lane owns 8 features (R8-proven form), fp32 accum.
// ---------------------------------------------------------------------------
#define GATHER_BLOCKS (NN * 32 / 256)            // 6250
#define CVTX_GROUPS (NN * FF / 8)                // 1,600,000
#define CVTX_BLOCKS ((CVTX_GROUPS + 255) / 256)  // 6250
#define CVTW_THREADS (2 * KK * FF * (FF / 8))    // 65536
#define CVTW_BLOCKS (CVTW_THREADS / 256)         // 256

__global__ __launch_bounds__(256) void prep_kernel(
    const float* __restrict__ x, const float* __restrict__ wi,
    const float* __restrict__ wr)
{
    const int bid = blockIdx.x;
    if (bid < GATHER_BLOCKS) {
        const int warp = (bid * 256 + threadIdx.x) >> 5;
        const int lane = threadIdx.x & 31;
        const int n = warp;
        const int f = lane * 8;

        float4 a0 = make_float4(0.f, 0.f, 0.f, 0.f);
        float4 a1 = make_float4(0.f, 0.f, 0.f, 0.f);
        const int beg = g_rowstart[n];
        const int end = g_rowstart[n + 1];
        int e = beg;
        for (; e + 1 < end; e += 2) {
            const int s0 = g_csr_src[e],  s1 = g_csr_src[e + 1];
            const float w0 = g_csr_w[e],  w1 = g_csr_w[e + 1];
            const float* p0 = x + (size_t)s0 * FF + f;
            const float* p1 = x + (size_t)s1 * FF + f;
            float4 u0 = *(const float4*)(p0);
            float4 u1 = *(const float4*)(p0 + 4);
            float4 v0 = *(const float4*)(p1);
            float4 v1 = *(const float4*)(p1 + 4);
            a0.x += w0 * u0.x + w1 * v0.x;  a0.y += w0 * u0.y + w1 * v0.y;
            a0.z += w0 * u0.z + w1 * v0.z;  a0.w += w0 * u0.w + w1 * v0.w;
            a1.x += w0 * u1.x + w1 * v1.x;  a1.y += w0 * u1.y + w1 * v1.y;
            a1.z += w0 * u1.z + w1 * v1.z;  a1.w += w0 * u1.w + w1 * v1.w;
        }
        if (e < end) {
            const int s0 = g_csr_src[e];
            const float w0 = g_csr_w[e];
            const float* p0 = x + (size_t)s0 * FF + f;
            float4 u0 = *(const float4*)(p0);
            float4 u1 = *(const float4*)(p0 + 4);
            a0.x += w0 * u0.x; a0.y += w0 * u0.y; a0.z += w0 * u0.z; a0.w += w0 * u0.w;
            a1.x += w0 * u1.x; a1.y += w0 * u1.y; a1.z += w0 * u1.z; a1.w += w0 * u1.w;
        }
        *(uint4*)(g_xph + (size_t)n * (FF / 2) + lane * 4) =
            make_uint4(pack_h2(a0.x, a0.y), pack_h2(a0.z, a0.w),
                       pack_h2(a1.x, a1.y), pack_h2(a1.z, a1.w));
    } else if (bid < GATHER_BLOCKS + CVTX_BLOCKS) {
        const int gi = (bid - GATHER_BLOCKS) * 256 + threadIdx.x;
        if (gi < CVTX_GROUPS) {
            const float* p = x + (size_t)gi * 8;
            float4 v0 = *(const float4*)(p);
            float4 v1 = *(const float4*)(p + 4);
            *(uint4*)(g_xh + (size_t)gi * 4) =
                make_uint4(pack_h2(v0.x, v0.y), pack_h2(v0.z, v0.w),
                           pack_h2(v1.x, v1.y), pack_h2(v1.z, v1.w));
        }
    } else {
        // W^T: thread -> (mat 0..3, grp 0..31, n 0..255); reads col n, 8 k-rows
        const int ti = (bid - GATHER_BLOCKS - CVTX_BLOCKS) * 256 + threadIdx.x;
        if (ti < CVTW_THREADS) {
            const int n = ti & 255;
            const int grp = (ti >> 8) & 31;
            const int mat = ti >> 13;            // 0..3 = phase*2+km
            const int km = mat & 1;
            const float* src = ((mat < 2) ? wi : wr) + (size_t)km * FF * FF;
            float v[8];
#pragma unroll
            for (int j = 0; j < 8; ++j)
                v[j] = src[(size_t)(grp * 8 + j) * FF + n];
            *(uint4*)(&g_wh[mat >> 1][km][n][grp * 4]) =
                make_uint4(pack_h2(v[0], v[1]), pack_h2(v[2], v[3]),
                           pack_h2(v[4], v[5]), pack_h2(v[6], v[7]));
        }
    }
}

// ---------------------------------------------------------------------------
// 6) Fused fp16 GEMM + epilogue; cp.async 3-stage.
// Block 128(M) x 128(N), BK=32 halves, 512 threads (4Mx4N warps, 32x32 warp tile).
// As[128 rows][20 words], Bs[2*128 n][20 words]; stride 20 => conflict-free.
// ---------------------------------------------------------------------------
#define AS_STRIDE 20
#define AS_WORDS (128 * AS_STRIDE)                 // 2560
#define BS_WORDS (2 * 128 * AS_STRIDE)             // 5120
#define STAGE_WORDS (AS_WORDS + BS_WORDS)          // 7680
#define NSTAGES 3
#define GEMM_SMEM (NSTAGES * STAGE_WORDS * 4)      // 92160 B

__device__ __forceinline__ void cp16(unsigned smaddr, const void* gptr, int valid) {
    asm volatile("cp.async.cg.shared.global [%0], [%1], 16, %2;"
                 :: "r"(smaddr), "l"(gptr), "r"(valid ? 16 : 0));
}
__device__ __forceinline__ void cp_commit() {
    asm volatile("cp.async.commit_group;");
}
template <int N>
__device__ __forceinline__ void cp_wait() {
    asm volatile("cp.async.wait_group %0;" :: "n"(N));
}

__device__ __forceinline__ void mma_f16(float* c, const unsigned* a, const unsigned* b) {
    asm volatile(
        "mma.sync.aligned.m16n8k16.row.col.f32.f16.f16.f32 "
        "{%0,%1,%2,%3}, {%4,%5,%6,%7}, {%8,%9}, {%0,%1,%2,%3};\n"
        : "+f"(c[0]), "+f"(c[1]), "+f"(c[2]), "+f"(c[3])
        : "r"(a[0]), "r"(a[1]), "r"(a[2]), "r"(a[3]), "r"(b[0]), "r"(b[1]));
}

__global__ __launch_bounds__(512, 1) void fused_gemm_kernel(
    const float* __restrict__ x, const float* __restrict__ bias,
    float* __restrict__ out)
{
    extern __shared__ unsigned sm[];

    const int tid = threadIdx.x;
    const int lane = tid & 31;
    const int wid = tid >> 5;
    const int warpM = wid & 3;
    const int warpN = wid >> 2;
    const int tileRow = blockIdx.y * 128;
    const int colBase = blockIdx.x * 128;

    auto issue = [&](int it, int st) {
        const int phase = it >> 3;
        const int kw = (it & 7) * 16;                 // word offset within 128-word row
        const unsigned* Ah = phase ? g_xh : g_xph;
        unsigned* As = sm + st * STAGE_WORDS;
        unsigned* Bs = As + AS_WORDS;
        unsigned as_base = (unsigned)__cvta_generic_to_shared(As);
        unsigned bs_base = (unsigned)__cvta_generic_to_shared(Bs);
        // A: 128 rows x 16 words = 512 cp16 -> 1 per thread
        {
            int m = tid >> 2, c = tid & 3;
            int row = tileRow + m;
            int valid = row < NN;
            int rowc = valid ? row : 0;
            cp16(as_base + (m * AS_STRIDE + c * 4) * 4,
                 Ah + (size_t)rowc * (FF / 2) + kw + c * 4, valid);
        }
        // B: 256 rows x 16 words = 1024 cp16 -> 2 per thread
#pragma unroll
        for (int i = 0; i < 2; ++i) {
            int ii = i * 512 + tid;
            int km = ii >> 9, n = (ii >> 2) & 127, c = ii & 3;
            cp16(bs_base + ((km * 128 + n) * AS_STRIDE + c * 4) * 4,
                 &g_wh[phase][km][colBase + n][kw + c * 4], 1);
        }
        cp_commit();
    };

    float acc[2][2][4][4] = {};   // [km][mt][nt][c]

    issue(0, 0);
    issue(1, 1);
    issue(2, 2);

    for (int it = 0; it < KITERS; ++it) {
        if (it < KITERS - 2)       cp_wait<2>();
        else if (it == KITERS - 2) cp_wait<1>();
        else                       cp_wait<0>();
        __syncthreads();

        const int st = it % NSTAGES;
        const unsigned* As = sm + st * STAGE_WORDS;
        const unsigned* Bs = As + AS_WORDS;
        const int q = lane & 3;
        const int g = lane >> 2;

#pragma unroll
        for (int ks = 0; ks < 2; ++ks) {              // two k16 steps per BK=32
            const int kb = ks * 8;
            unsigned a[2][4];
#pragma unroll
            for (int mt = 0; mt < 2; ++mt) {
                int mrow = warpM * 32 + mt * 16 + g;
                const unsigned* r0 = As + mrow * AS_STRIDE + kb + q;
                const unsigned* r1 = As + (mrow + 8) * AS_STRIDE + kb + q;
                a[mt][0] = r0[0];
                a[mt][1] = r1[0];
                a[mt][2] = r0[4];
                a[mt][3] = r1[4];
            }
            unsigned b[2][4][2];
#pragma unroll
            for (int km = 0; km < 2; ++km)
#pragma unroll
                for (int nt = 0; nt < 4; ++nt) {
                    int ncol = warpN * 32 + nt * 8 + g;
                    const unsigned* bp = Bs + (km * 128 + ncol) * AS_STRIDE + kb + q;
                    b[km][nt][0] = bp[0];
                    b[km][nt][1] = bp[4];
                }
#pragma unroll
            for (int km = 0; km < 2; ++km)
#pragma unroll
                for (int mt = 0; mt < 2; ++mt)
#pragma unroll
                    for (int nt = 0; nt < 4; ++nt)
                        mma_f16(acc[km][mt][nt], a[mt], b[km][nt]);
        }
        __syncthreads();
        if (it + NSTAGES < KITERS) issue(it + NSTAGES, st);
    }

    // Epilogue: out = x + relu(0.5*(relu(C0+b0)+relu(C1+b1)))
#pragma unroll
    for (int mt = 0; mt < 2; ++mt) {
#pragma unroll
        for (int nt = 0; nt < 4; ++nt) {
            const int col = colBase + warpN * 32 + nt * 8 + 2 * (lane & 3);
            const float bi00 = bias[col],      bi01 = bias[col + 1];
            const float bi10 = bias[FF + col], bi11 = bias[FF + col + 1];
            const int r0 = tileRow + warpM * 32 + mt * 16 + (lane >> 2);

            if (r0 < NN) {
                float2 xv = *(const float2*)(x + (size_t)r0 * FF + col);
                float u0 = fmaxf(acc[0][mt][nt][0] + bi00, 0.f);
                float v0 = fmaxf(acc[1][mt][nt][0] + bi10, 0.f);
                float u1 = fmaxf(acc[0][mt][nt][1] + bi01, 0.f);
                float v1 = fmaxf(acc[1][mt][nt][1] + bi11, 0.f);
                float2 o;
                o.x = xv.x + fmaxf(0.5f * (u0 + v0), 0.f);
                o.y = xv.y + fmaxf(0.5f * (u1 + v1), 0.f);
                *(float2*)(out + (size_t)r0 * FF + col) = o;
            }
            const int r1 = r0 + 8;
            if (r1 < NN) {
                float2 xv = *(const float2*)(x + (size_t)r1 * FF + col);
                float u0 = fmaxf(acc[0][mt][nt][2] + bi00, 0.f);
                float v0 = fmaxf(acc[1][mt][nt][2] + bi10, 0.f);
                float u1 = fmaxf(acc[0][mt][nt][3] + bi01, 0.f);
                float v1 = fmaxf(acc[1][mt][nt][3] + bi11, 0.f);
                float2 o;
                o.x = xv.x + fmaxf(0.5f * (u0 + v0), 0.f);
                o.y = xv.y + fmaxf(0.5f * (u1 + v1), 0.f);
                *(float2*)(out + (size_t)r1 * FF + col) = o;
            }
        }
    }
}

// ---------------------------------------------------------------------------
// launch: 6 kernels, GEMM is #6 (ncu -s 5 -c 1 captures it)
// ---------------------------------------------------------------------------
extern "C" void kernel_launch(void* const* d_in, const int* in_sizes, int n_in,
                              void* d_out, int out_size) {
    const float* x    = (const float*)d_in[0];
    const void* ei    = d_in[1];
    const float* wi   = (const float*)d_in[2];
    const float* wr   = (const float*)d_in[3];
    const float* bias = (const float*)d_in[4];
    float* out        = (float*)d_out;

    static int smem_set = 0;
    if (!smem_set) {
        cudaFuncSetAttribute(fused_gemm_kernel,
                             cudaFuncAttributeMaxDynamicSharedMemorySize, GEMM_SMEM);
        smem_set = 1;
    }

    zero_sniff_kernel<<<(NN + 255) / 256, 256>>>((const int*)ei);               // 1
    deg_kernel<<<(EE + 255) / 256, 256>>>(ei);                                  // 2
    scan_kernel<<<1, 1024>>>();                                                 // 3
    fill_csr_kernel<<<(EE + 255) / 256, 256>>>(ei);                             // 4
    prep_kernel<<<GATHER_BLOCKS + CVTX_BLOCKS + CVTW_BLOCKS, 256>>>(x, wi, wr); // 5
    dim3 ggrid(FF / 128, (NN + 127) / 128);                                     // (2, 391)
    fused_gemm_kernel<<<ggrid, 512, GEMM_SMEM>>>(x, bias, out);                 // 6
}

// round 11
// speedup vs baseline: 1.3512x; 1.0472x over previous
#include <cuda_runtime.h>
#include <cuda_fp16.h>
#include <stdint.h>

#define NN 50000
#define EE 320000
#define FF 256
#define KK 2
#define KDIM 512
#define KITERS 16        // KDIM / 32 (BK = 32 halves)

// Scratch (allocation-free rule: __device__ globals). fp16 packed as half2 words.
__device__ unsigned g_xph[(size_t)NN * FF / 2];      // half2(A_hat @ x)
__device__ unsigned g_xh[(size_t)NN * FF / 2];       // half2(x)
__device__ unsigned g_wh[2][KK][FF][FF / 2];         // half2 W^T, k-permuted per 8-word group
__device__ int   g_degi[NN];
__device__ float g_dinv[NN];
__device__ int   g_rowstart[NN + 1];
__device__ int   g_cursor[NN];
__device__ int   g_csr_src[EE];
__device__ float g_csr_w[EE];
__device__ int   g_is64;

__device__ __forceinline__ unsigned pack_h2(float a, float b) {
    __half2 h = __floats2half2_rn(a, b);
    return *(unsigned*)&h;
}
__device__ __forceinline__ float2 h2f2(unsigned u) {
    return __half22float2(*(__half2*)&u);
}
__device__ __forceinline__ int load_idx(const void* ei, int which, int e) {
    if (g_is64) return (int)((const long long*)ei)[(size_t)which * EE + e];
    return ((const int*)ei)[(size_t)which * EE + e];
}

// ---------------------------------------------------------------------------
// 1) zero degrees + sniff + cvt_x + cvt_w  (all dependency-free work)
// ---------------------------------------------------------------------------
#define ZERO_BLOCKS ((NN + 255) / 256)            // 196
#define CVTX_GROUPS (NN * FF / 8)                 // 1,600,000
#define CVTX_BLOCKS ((CVTX_GROUPS + 255) / 256)   // 6250
#define CVTW_THREADS (2 * KK * FF * (FF / 16))    // 16384 (16 k per thread)
#define CVTW_BLOCKS (CVTW_THREADS / 256)          // 64

__global__ __launch_bounds__(256) void init_kernel(
    const float* __restrict__ x, const float* __restrict__ wi,
    const float* __restrict__ wr, const int* __restrict__ ei32)
{
    const int bid = blockIdx.x;
    if (bid < ZERO_BLOCKS) {
        int i = bid * 256 + threadIdx.x;
        if (i < NN) g_degi[i] = 0;
        if (bid == 0 && threadIdx.x == 0) {
            int any = 0;
            for (int j = 0; j < 256; ++j) any |= ei32[2 * j + 1];
            g_is64 = (any == 0) ? 1 : 0;
        }
    } else if (bid < ZERO_BLOCKS + CVTX_BLOCKS) {
        const int gi = (bid - ZERO_BLOCKS) * 256 + threadIdx.x;
        if (gi < CVTX_GROUPS) {
            const float* p = x + (size_t)gi * 8;
            float4 v0 = *(const float4*)(p);
            float4 v1 = *(const float4*)(p + 4);
            *(uint4*)(g_xh + (size_t)gi * 4) =
                make_uint4(pack_h2(v0.x, v0.y), pack_h2(v0.z, v0.w),
                           pack_h2(v1.x, v1.y), pack_h2(v1.z, v1.w));
        }
    } else {
        // W^T with k-group permutation {0,4,1,5,2,6,3,7} (words within 16-k group)
        const int ti = (bid - ZERO_BLOCKS - CVTX_BLOCKS) * 256 + threadIdx.x;
        if (ti < CVTW_THREADS) {
            const int n = ti & 255;
            const int grp = (ti >> 8) & 15;       // 16 k-values per group
            const int mat = ti >> 12;             // 0..3 = phase*2+km
            const int km = mat & 1;
            const float* src = ((mat < 2) ? wi : wr) + (size_t)km * FF * FF;
            float v[16];
#pragma unroll
            for (int j = 0; j < 16; ++j)
                v[j] = src[(size_t)(grp * 16 + j) * FF + n];
            unsigned w[8];
#pragma unroll
            for (int q = 0; q < 8; ++q) w[q] = pack_h2(v[2 * q], v[2 * q + 1]);
            unsigned* o = &g_wh[mat >> 1][km][n][grp * 8];
            *(uint4*)(o)     = make_uint4(w[0], w[4], w[1], w[5]);
            *(uint4*)(o + 4) = make_uint4(w[2], w[6], w[3], w[7]);
        }
    }
}

// ---------------------------------------------------------------------------
// 2) degree count
// ---------------------------------------------------------------------------
__global__ void deg_kernel(const void* __restrict__ ei) {
    int e = blockIdx.x * blockDim.x + threadIdx.x;
    if (e < EE) atomicAdd(&g_degi[load_idx(ei, 1, e)], 1);
}

// ---------------------------------------------------------------------------
// 3) scan (+ dinv folded in)
// ---------------------------------------------------------------------------
#define SCAN_CH 49

__global__ __launch_bounds__(1024) void scan_kernel() {
    __shared__ int s[1024];
    const int t = threadIdx.x;
    const int base = t * SCAN_CH;
    int sum = 0;
#pragma unroll
    for (int i = 0; i < SCAN_CH; ++i) {
        int idx = base + i;
        if (idx < NN) {
            int d = g_degi[idx];
            sum += d;
            g_dinv[idx] = (d > 0) ? rsqrtf((float)d) : 0.0f;
        }
    }
    s[t] = sum;
    __syncthreads();
    for (int off = 1; off < 1024; off <<= 1) {
        int v = (t >= off) ? s[t - off] : 0;
        __syncthreads();
        s[t] += v;
        __syncthreads();
    }
    int run = (t == 0) ? 0 : s[t - 1];
#pragma unroll
    for (int i = 0; i < SCAN_CH; ++i) {
        int idx = base + i;
        if (idx < NN) {
            g_rowstart[idx] = run;
            run += g_degi[idx];
            g_cursor[idx] = 0;
        }
    }
    if (t == 1023) g_rowstart[NN] = run;
}

// ---------------------------------------------------------------------------
// 4) CSR fill
// ---------------------------------------------------------------------------
__global__ void fill_csr_kernel(const void* __restrict__ ei) {
    int e = blockIdx.x * blockDim.x + threadIdx.x;
    if (e >= EE) return;
    int src = load_idx(ei, 0, e);
    int dst = load_idx(ei, 1, e);
    int pos = atomicAdd(&g_cursor[dst], 1);
    int idx = g_rowstart[dst] + pos;
    g_csr_src[idx] = src;
    g_csr_w[idx] = g_dinv[src] * g_dinv[dst];
}

// ---------------------------------------------------------------------------
// 5) gather: xp = A_hat @ x, fp16 in (g_xh), fp32 accum, fp16 out.
//    Warp per node; lane owns 8 features = one uint4 per edge.
// ---------------------------------------------------------------------------
__global__ __launch_bounds__(256) void gather_kernel() {
    const int warp = (blockIdx.x * blockDim.x + threadIdx.x) >> 5;
    const int lane = threadIdx.x & 31;
    if (warp >= NN) return;
    const int n = warp;

    float4 a0 = make_float4(0.f, 0.f, 0.f, 0.f);
    float4 a1 = make_float4(0.f, 0.f, 0.f, 0.f);
    const int beg = g_rowstart[n];
    const int end = g_rowstart[n + 1];
    int e = beg;
    for (; e + 1 < end; e += 2) {
        const int s0 = g_csr_src[e], s1 = g_csr_src[e + 1];
        const float w0 = g_csr_w[e], w1 = g_csr_w[e + 1];
        uint4 u = *(const uint4*)(g_xh + (size_t)s0 * (FF / 2) + lane * 4);
        uint4 v = *(const uint4*)(g_xh + (size_t)s1 * (FF / 2) + lane * 4);
        float2 p;
        p = h2f2(u.x); a0.x += w0 * p.x; a0.y += w0 * p.y;
        p = h2f2(u.y); a0.z += w0 * p.x; a0.w += w0 * p.y;
        p = h2f2(u.z); a1.x += w0 * p.x; a1.y += w0 * p.y;
        p = h2f2(u.w); a1.z += w0 * p.x; a1.w += w0 * p.y;
        p = h2f2(v.x); a0.x += w1 * p.x; a0.y += w1 * p.y;
        p = h2f2(v.y); a0.z += w1 * p.x; a0.w += w1 * p.y;
        p = h2f2(v.z); a1.x += w1 * p.x; a1.y += w1 * p.y;
        p = h2f2(v.w); a1.z += w1 * p.x; a1.w += w1 * p.y;
    }
    if (e < end) {
        const int s0 = g_csr_src[e];
        const float w0 = g_csr_w[e];
        uint4 u = *(const uint4*)(g_xh + (size_t)s0 * (FF / 2) + lane * 4);
        float2 p;
        p = h2f2(u.x); a0.x += w0 * p.x; a0.y += w0 * p.y;
        p = h2f2(u.y); a0.z += w0 * p.x; a0.w += w0 * p.y;
        p = h2f2(u.z); a1.x += w0 * p.x; a1.y += w0 * p.y;
        p = h2f2(u.w); a1.z += w0 * p.x; a1.w += w0 * p.y;
    }
    *(uint4*)(g_xph + (size_t)n * (FF / 2) + lane * 4) =
        make_uint4(pack_h2(a0.x, a0.y), pack_h2(a0.z, a0.w),
                   pack_h2(a1.x, a1.y), pack_h2(a1.z, a1.w));
}

// ---------------------------------------------------------------------------
// 6) Fused fp16 GEMM + epilogue; cp.async 4-stage, ONE sync per iter.
// Block 128(M) x 128(N), BK=32 halves, 512 threads (4Mx4N warps, 32x32 warp tile).
// As stride 20 (scalar LDS conflict-free), Bs stride 24 (uint2 LDS conflict-free).
// ---------------------------------------------------------------------------
#define AS_STRIDE 20
#define BS_STRIDE 24
#define AS_WORDS (128 * AS_STRIDE)                 // 2560
#define BS_WORDS (2 * 128 * BS_STRIDE)             // 6144
#define STAGE_WORDS (AS_WORDS + BS_WORDS)          // 8704
#define NSTAGES 4
#define GEMM_SMEM (NSTAGES * STAGE_WORDS * 4)      // 139264 B

__device__ __forceinline__ void cp16(unsigned smaddr, const void* gptr, int valid) {
    asm volatile("cp.async.cg.shared.global [%0], [%1], 16, %2;"
                 :: "r"(smaddr), "l"(gptr), "r"(valid ? 16 : 0));
}
__device__ __forceinline__ void cp_commit() {
    asm volatile("cp.async.commit_group;");
}
template <int N>
__device__ __forceinline__ void cp_wait() {
    asm volatile("cp.async.wait_group %0;" :: "n"(N));
}

__device__ __forceinline__ void mma_f16(float* c, const unsigned* a, const unsigned* b) {
    asm volatile(
        "mma.sync.aligned.m16n8k16.row.col.f32.f16.f16.f32 "
        "{%0,%1,%2,%3}, {%4,%5,%6,%7}, {%8,%9}, {%0,%1,%2,%3};\n"
        : "+f"(c[0]), "+f"(c[1]), "+f"(c[2]), "+f"(c[3])
        : "r"(a[0]), "r"(a[1]), "r"(a[2]), "r"(a[3]), "r"(b[0]), "r"(b[1]));
}

__global__ __launch_bounds__(512, 1) void fused_gemm_kernel(
    const float* __restrict__ x, const float* __restrict__ bias,
    float* __restrict__ out)
{
    extern __shared__ unsigned sm[];

    const int tid = threadIdx.x;
    const int lane = tid & 31;
    const int wid = tid >> 5;
    const int warpM = wid & 3;
    const int warpN = wid >> 2;
    const int tileRow = blockIdx.y * 128;
    const int colBase = blockIdx.x * 128;

    auto issue = [&](int it, int st) {
        const int phase = it >> 3;
        const int kw = (it & 7) * 16;                 // word offset within row
        const unsigned* Ah = phase ? g_xh : g_xph;
        unsigned* As = sm + st * STAGE_WORDS;
        unsigned* Bs = As + AS_WORDS;
        unsigned as_base = (unsigned)__cvta_generic_to_shared(As);
        unsigned bs_base = (unsigned)__cvta_generic_to_shared(Bs);
        // A: 128 rows x 16 words -> 1 cp16 per thread
        {
            int m = tid >> 2, c = tid & 3;
            int row = tileRow + m;
            int valid = row < NN;
            int rowc = valid ? row : 0;
            cp16(as_base + (m * AS_STRIDE + c * 4) * 4,
                 Ah + (size_t)rowc * (FF / 2) + kw + c * 4, valid);
        }
        // B: 256 (km,n) rows x 16 words -> 2 cp16 per thread (permuted layout copied verbatim)
#pragma unroll
        for (int i = 0; i < 2; ++i) {
            int ii = i * 512 + tid;
            int km = ii >> 9, n = (ii >> 2) & 127, c = ii & 3;
            cp16(bs_base + ((km * 128 + n) * BS_STRIDE + c * 4) * 4,
                 &g_wh[phase][km][colBase + n][kw + c * 4], 1);
        }
        cp_commit();
    };

    float acc[2][2][4][4] = {};   // [km][mt][nt][c]

    issue(0, 0);
    issue(1, 1);
    issue(2, 2);

    for (int it = 0; it < KITERS; ++it) {
        if (it < KITERS - 2)       cp_wait<2>();
        else if (it == KITERS - 2) cp_wait<1>();
        else                       cp_wait<0>();
        __syncthreads();
        if (it + 3 < KITERS) issue(it + 3, (it + 3) % NSTAGES);

        const unsigned* As = sm + (it % NSTAGES) * STAGE_WORDS;
        const unsigned* Bs = As + AS_WORDS;
        const int q = lane & 3;
        const int g = lane >> 2;

#pragma unroll
        for (int ks = 0; ks < 2; ++ks) {              // two k16 steps per BK=32
            const int kb = ks * 8;
            unsigned a[2][4];
#pragma unroll
            for (int mt = 0; mt < 2; ++mt) {
                int mrow = warpM * 32 + mt * 16 + g;
                const unsigned* r0 = As + mrow * AS_STRIDE + kb + q;
                const unsigned* r1 = As + (mrow + 8) * AS_STRIDE + kb + q;
                a[mt][0] = r0[0];
                a[mt][1] = r1[0];
                a[mt][2] = r0[4];
                a[mt][3] = r1[4];
            }
            uint2 b[2][4];
#pragma unroll
            for (int km = 0; km < 2; ++km)
#pragma unroll
                for (int nt = 0; nt < 4; ++nt) {
                    int ncol = warpN * 32 + nt * 8 + g;
                    b[km][nt] = *(const uint2*)(Bs + (km * 128 + ncol) * BS_STRIDE
                                                + kb + 2 * q);
                }
#pragma unroll
            for (int km = 0; km < 2; ++km)
#pragma unroll
                for (int mt = 0; mt < 2; ++mt)
#pragma unroll
                    for (int nt = 0; nt < 4; ++nt)
                        mma_f16(acc[km][mt][nt], a[mt], (const unsigned*)&b[km][nt]);
        }
    }

    // Epilogue: out = x + relu(0.5*(relu(C0+b0)+relu(C1+b1)))
#pragma unroll
    for (int mt = 0; mt < 2; ++mt) {
#pragma unroll
        for (int nt = 0; nt < 4; ++nt) {
            const int col = colBase + warpN * 32 + nt * 8 + 2 * (lane & 3);
            const float bi00 = bias[col],      bi01 = bias[col + 1];
            const float bi10 = bias[FF + col], bi11 = bias[FF + col + 1];
            const int r0 = tileRow + warpM * 32 + mt * 16 + (lane >> 2);

            if (r0 < NN) {
                float2 xv = *(const float2*)(x + (size_t)r0 * FF + col);
                float u0 = fmaxf(acc[0][mt][nt][0] + bi00, 0.f);
                float v0 = fmaxf(acc[1][mt][nt][0] + bi10, 0.f);
                float u1 = fmaxf(acc[0][mt][nt][1] + bi01, 0.f);
                float v1 = fmaxf(acc[1][mt][nt][1] + bi11, 0.f);
                float2 o;
                o.x = xv.x + fmaxf(0.5f * (u0 + v0), 0.f);
                o.y = xv.y + fmaxf(0.5f * (u1 + v1), 0.f);
                *(float2*)(out + (size_t)r0 * FF + col) = o;
            }
            const int r1 = r0 + 8;
            if (r1 < NN) {
                float2 xv = *(const float2*)(x + (size_t)r1 * FF + col);
                float u0 = fmaxf(acc[0][mt][nt][2] + bi00, 0.f);
                float v0 = fmaxf(acc[1][mt][nt][2] + bi10, 0.f);
                float u1 = fmaxf(acc[0][mt][nt][3] + bi01, 0.f);
                float v1 = fmaxf(acc[1][mt][nt][3] + bi11, 0.f);
                float2 o;
                o.x = xv.x + fmaxf(0.5f * (u0 + v0), 0.f);
                o.y = xv.y + fmaxf(0.5f * (u1 + v1), 0.f);
                *(float2*)(out + (size_t)r1 * FF + col) = o;
            }
        }
    }
}

// ---------------------------------------------------------------------------
// launch: 6 kernels
// ---------------------------------------------------------------------------
extern "C" void kernel_launch(void* const* d_in, const int* in_sizes, int n_in,
                              void* d_out, int out_size) {
    const float* x    = (const float*)d_in[0];
    const void* ei    = d_in[1];
    const float* wi   = (const float*)d_in[2];
    const float* wr   = (const float*)d_in[3];
    const float* bias = (const float*)d_in[4];
    float* out        = (float*)d_out;

    static int smem_set = 0;
    if (!smem_set) {
        cudaFuncSetAttribute(fused_gemm_kernel,
                             cudaFuncAttributeMaxDynamicSharedMemorySize, GEMM_SMEM);
        smem_set = 1;
    }

    init_kernel<<<ZERO_BLOCKS + CVTX_BLOCKS + CVTW_BLOCKS, 256>>>(
        x, wi, wr, (const int*)ei);                                       // 1
    deg_kernel<<<(EE + 255) / 256, 256>>>(ei);                            // 2
    scan_kernel<<<1, 1024>>>();                                           // 3
    fill_csr_kernel<<<(EE + 255) / 256, 256>>>(ei);                       // 4
    gather_kernel<<<(NN * 32 + 255) / 256, 256>>>();                      // 5
    dim3 ggrid(FF / 128, (NN + 127) / 128);                               // (2, 391)
    fused_gemm_kernel<<<ggrid, 512, GEMM_SMEM>>>(x, bias, out);           // 6
}